// round 1
// baseline (speedup 1.0000x reference)
#include <cuda_runtime.h>

// ============================================================================
// EncoderLayer: x -> MHA(+residual,LN) -> FFN(+residual,LN)
// B=4, S=2048, D=1024, H=16, HD=64, M=4096.  fp32 baseline.
// ============================================================================

#define NROWS 8192   // B*S
#define DM    1024
#define MFF   4096
#define SEQ   2048
#define NB    4
#define NH    16

// Scratch (device globals: allocation-free per harness rules)
__device__ float g_q  [NROWS * DM];
__device__ float g_k  [NROWS * DM];
__device__ float g_v  [NROWS * DM];
__device__ float g_ctx[NROWS * DM];
__device__ float g_t0 [NROWS * DM];
__device__ float g_x1 [NROWS * DM];
__device__ float g_ffh[(size_t)NROWS * MFF];
__device__ float g_ff2[NROWS * DM];

// ----------------------------------------------------------------------------
// SGEMM: C[M,N] = A[M,K] @ B[K,N] (+bias, +relu).  128x128 tile, 8x8 micro.
// Requires M%128==0, N%128==0, K%8==0 (all shapes here comply).
// MODE bit0 = add bias[col], bit1 = relu.
// ----------------------------------------------------------------------------
template<int MODE>
__global__ __launch_bounds__(256) void sgemm(
    const float* __restrict__ A, const float* __restrict__ B,
    const float* __restrict__ bias, float* __restrict__ C,
    int M, int N, int K)
{
    __shared__ float As[8][128];
    __shared__ float Bs[8][128];
    const int tid = threadIdx.x;
    const int m0 = blockIdx.y * 128;
    const int n0 = blockIdx.x * 128;
    const int aRow = tid >> 1, aCol = (tid & 1) * 4;   // A tile: 128x8 via float4
    const int bRow = tid >> 5, bCol = (tid & 31) * 4;  // B tile: 8x128 via float4
    const int tx = tid & 15, ty = tid >> 4;

    const float* Ap = A + (size_t)(m0 + aRow) * K + aCol;
    const float* Bp = B + (size_t)bRow * N + n0 + bCol;

    float acc[8][8];
    #pragma unroll
    for (int i = 0; i < 8; i++)
        #pragma unroll
        for (int j = 0; j < 8; j++) acc[i][j] = 0.f;

    for (int k0 = 0; k0 < K; k0 += 8) {
        float4 a4 = *(const float4*)(Ap + k0);
        float4 b4 = *(const float4*)(Bp + (size_t)k0 * N);
        __syncthreads();
        As[aCol + 0][aRow] = a4.x;
        As[aCol + 1][aRow] = a4.y;
        As[aCol + 2][aRow] = a4.z;
        As[aCol + 3][aRow] = a4.w;
        *(float4*)&Bs[bRow][bCol] = b4;
        __syncthreads();
        #pragma unroll
        for (int k = 0; k < 8; k++) {
            float ar[8], br[8];
            #pragma unroll
            for (int i = 0; i < 8; i++) ar[i] = As[k][ty * 8 + i];
            #pragma unroll
            for (int j = 0; j < 8; j++) br[j] = Bs[k][tx * 8 + j];
            #pragma unroll
            for (int i = 0; i < 8; i++)
                #pragma unroll
                for (int j = 0; j < 8; j++)
                    acc[i][j] = fmaf(ar[i], br[j], acc[i][j]);
        }
    }

    #pragma unroll
    for (int i = 0; i < 8; i++) {
        const size_t row = (size_t)(m0 + ty * 8 + i);
        float vs[8];
        #pragma unroll
        for (int j = 0; j < 8; j++) {
            float v = acc[i][j];
            if (MODE & 1) v += bias[n0 + tx * 8 + j];
            if (MODE & 2) v = fmaxf(v, 0.f);
            vs[j] = v;
        }
        float4* cp = (float4*)(C + row * N + n0 + tx * 8);
        cp[0] = make_float4(vs[0], vs[1], vs[2], vs[3]);
        cp[1] = make_float4(vs[4], vs[5], vs[6], vs[7]);
    }
}

// ----------------------------------------------------------------------------
// Flash attention: per block = (q-tile of 64, head, batch). 256 threads.
// Online softmax over 32 kv-tiles of 64.  Q pre-scaled by D^-0.5 = 1/32.
// Dynamic smem: Qst[64][65] (d-major), Kst[64][65] (d-major), Vs[64][65],
//               Ss[64][65], m/l/corr[64].
// ----------------------------------------------------------------------------
#define ATT_LD 65
#define ATT_SMEM_FLOATS (4 * 64 * ATT_LD + 3 * 64)
#define ATT_SMEM_BYTES  (ATT_SMEM_FLOATS * 4)

__global__ __launch_bounds__(256) void attn_kernel(
    const float* __restrict__ q, const float* __restrict__ k,
    const float* __restrict__ v, const unsigned char* __restrict__ mask,
    float* __restrict__ ctx)
{
    extern __shared__ float sm[];
    float* Qst = sm;                    // [d][r]
    float* Kst = Qst + 64 * ATT_LD;     // [d][c]
    float* Vs  = Kst + 64 * ATT_LD;     // [c][d]
    float* Ss  = Vs  + 64 * ATT_LD;     // [r][c] scores -> probs
    float* m_s = Ss  + 64 * ATT_LD;
    float* l_s = m_s + 64;
    float* c_s = l_s + 64;

    const int t  = threadIdx.x;
    const int qt = blockIdx.x, h = blockIdx.y, b = blockIdx.z;
    const int s0 = qt * 64;
    const int tx = t & 15, ty = t >> 4;
    const float scale = 0.03125f;  // 1024^-0.5

    const float* qbase = q + ((size_t)b * SEQ + s0) * DM + h * 64;
    const float* kbase = k + (size_t)b * SEQ * DM + h * 64;
    const float* vbase = v + (size_t)b * SEQ * DM + h * 64;

    #pragma unroll
    for (int i = 0; i < 16; i++) {
        int id = t + i * 256;
        int r = id >> 6, d = id & 63;
        Qst[d * ATT_LD + r] = qbase[(size_t)r * DM + d] * scale;
    }
    if (t < 64) { m_s[t] = -1e30f; l_s[t] = 0.f; }

    float acc[4][4];
    #pragma unroll
    for (int i = 0; i < 4; i++)
        #pragma unroll
        for (int j = 0; j < 4; j++) acc[i][j] = 0.f;

    for (int kt = 0; kt < 32; kt++) {
        __syncthreads();   // previous iteration's reads of Kst/Vs/Ss complete
        #pragma unroll
        for (int i = 0; i < 16; i++) {
            int id = t + i * 256;
            int r = id >> 6, d = id & 63;
            size_t goff = (size_t)(kt * 64 + r) * DM + d;
            Kst[d * ATT_LD + r] = kbase[goff];
            Vs [r * ATT_LD + d] = vbase[goff];
        }
        __syncthreads();

        // ---- scores: 4x4 micro over 64x64 tile ----
        float sc[4][4];
        #pragma unroll
        for (int i = 0; i < 4; i++)
            #pragma unroll
            for (int j = 0; j < 4; j++) sc[i][j] = 0.f;
        #pragma unroll 8
        for (int d = 0; d < 64; d++) {
            float qv[4], kv[4];
            #pragma unroll
            for (int i = 0; i < 4; i++) qv[i] = Qst[d * ATT_LD + ty * 4 + i];
            #pragma unroll
            for (int j = 0; j < 4; j++) kv[j] = Kst[d * ATT_LD + tx * 4 + j];
            #pragma unroll
            for (int i = 0; i < 4; i++)
                #pragma unroll
                for (int j = 0; j < 4; j++)
                    sc[i][j] = fmaf(qv[i], kv[j], sc[i][j]);
        }
        const unsigned char* mrow =
            mask + ((size_t)b * SEQ + s0 + ty * 4) * SEQ + kt * 64 + tx * 4;
        #pragma unroll
        for (int i = 0; i < 4; i++)
            #pragma unroll
            for (int j = 0; j < 4; j++) {
                float s = sc[i][j];
                if (mrow[(size_t)i * SEQ + j]) s = -1e9f;
                Ss[(ty * 4 + i) * ATT_LD + tx * 4 + j] = s;
            }
        __syncthreads();

        // ---- online softmax: 4 lanes per row ----
        {
            const int r = t >> 2, qd = t & 3;
            float mold = m_s[r];
            float sv[16];
            float tm = -1e30f;
            #pragma unroll
            for (int c = 0; c < 16; c++) {
                sv[c] = Ss[r * ATT_LD + qd * 16 + c];
                tm = fmaxf(tm, sv[c]);
            }
            tm = fmaxf(tm, __shfl_xor_sync(0xffffffffu, tm, 1));
            tm = fmaxf(tm, __shfl_xor_sync(0xffffffffu, tm, 2));
            float mnew = fmaxf(mold, tm);
            float corr = __expf(mold - mnew);
            float ls = 0.f;
            #pragma unroll
            for (int c = 0; c < 16; c++) {
                float p = __expf(sv[c] - mnew);
                Ss[r * ATT_LD + qd * 16 + c] = p;
                ls += p;
            }
            ls += __shfl_xor_sync(0xffffffffu, ls, 1);
            ls += __shfl_xor_sync(0xffffffffu, ls, 2);
            if (qd == 0) {
                m_s[r] = mnew;
                l_s[r] = l_s[r] * corr + ls;
                c_s[r] = corr;
            }
        }
        __syncthreads();

        // ---- P @ V: rescale + accumulate ----
        float cr[4];
        #pragma unroll
        for (int i = 0; i < 4; i++) cr[i] = c_s[ty * 4 + i];
        #pragma unroll
        for (int i = 0; i < 4; i++)
            #pragma unroll
            for (int j = 0; j < 4; j++) acc[i][j] *= cr[i];
        #pragma unroll 8
        for (int c = 0; c < 64; c++) {
            float pv[4], vv[4];
            #pragma unroll
            for (int i = 0; i < 4; i++) pv[i] = Ss[(ty * 4 + i) * ATT_LD + c];
            #pragma unroll
            for (int j = 0; j < 4; j++) vv[j] = Vs[c * ATT_LD + tx * 4 + j];
            #pragma unroll
            for (int i = 0; i < 4; i++)
                #pragma unroll
                for (int j = 0; j < 4; j++)
                    acc[i][j] = fmaf(pv[i], vv[j], acc[i][j]);
        }
    }

    float* obase = ctx + ((size_t)b * SEQ + s0) * DM + h * 64;
    #pragma unroll
    for (int i = 0; i < 4; i++) {
        const int r = ty * 4 + i;
        const float inv_l = 1.0f / l_s[r];
        #pragma unroll
        for (int j = 0; j < 4; j++)
            obase[(size_t)r * DM + tx * 4 + j] = acc[i][j] * inv_l;
    }
}

// ----------------------------------------------------------------------------
// out = LayerNorm(a + res; gamma, beta), row length 1024, eps 1e-5.
// One block (256 thr) per row, 4 elements per thread.
// ----------------------------------------------------------------------------
__global__ __launch_bounds__(256) void add_ln_kernel(
    const float* __restrict__ a, const float* __restrict__ res,
    const float* __restrict__ gmm, const float* __restrict__ beta,
    float* __restrict__ out)
{
    const int row = blockIdx.x;
    const int t = threadIdx.x;
    const size_t base = (size_t)row * DM;
    float v[4];
    float s = 0.f, s2 = 0.f;
    #pragma unroll
    for (int i = 0; i < 4; i++) {
        int c = t + i * 256;
        float x = a[base + c] + res[base + c];
        v[i] = x; s += x; s2 += x * x;
    }
    #pragma unroll
    for (int o = 16; o > 0; o >>= 1) {
        s  += __shfl_down_sync(0xffffffffu, s,  o);
        s2 += __shfl_down_sync(0xffffffffu, s2, o);
    }
    __shared__ float sh[18];
    const int w = t >> 5;
    if ((t & 31) == 0) { sh[w] = s; sh[8 + w] = s2; }
    __syncthreads();
    if (t == 0) {
        float ts = 0.f, ts2 = 0.f;
        #pragma unroll
        for (int i = 0; i < 8; i++) { ts += sh[i]; ts2 += sh[8 + i]; }
        float mu  = ts * (1.0f / DM);
        float var = ts2 * (1.0f / DM) - mu * mu;
        sh[16] = mu;
        sh[17] = rsqrtf(var + 1e-5f);
    }
    __syncthreads();
    const float mu = sh[16], rs = sh[17];
    #pragma unroll
    for (int i = 0; i < 4; i++) {
        int c = t + i * 256;
        out[base + c] = (v[i] - mu) * rs * gmm[c] + beta[c];
    }
}

// ----------------------------------------------------------------------------
// kernel_launch
// inputs: 0=x 1=mask 2=Wq 3=Wk 4=Wv 5=Wo 6=W1 7=b1 8=W2 9=b2
//         10=g1 11=be1 12=g2 13=be2
// ----------------------------------------------------------------------------
extern "C" void kernel_launch(void* const* d_in, const int* in_sizes, int n_in,
                              void* d_out, int out_size)
{
    (void)in_sizes; (void)n_in; (void)out_size;
    const float* x  = (const float*)d_in[0];
    const unsigned char* mask = (const unsigned char*)d_in[1];
    const float* Wq = (const float*)d_in[2];
    const float* Wk = (const float*)d_in[3];
    const float* Wv = (const float*)d_in[4];
    const float* Wo = (const float*)d_in[5];
    const float* W1 = (const float*)d_in[6];
    const float* b1 = (const float*)d_in[7];
    const float* W2 = (const float*)d_in[8];
    const float* b2 = (const float*)d_in[9];
    const float* g1  = (const float*)d_in[10];
    const float* be1 = (const float*)d_in[11];
    const float* g2  = (const float*)d_in[12];
    const float* be2 = (const float*)d_in[13];
    float* out = (float*)d_out;

    float *q, *k, *v, *ctx, *t0, *x1, *ffh, *ff2;
    cudaGetSymbolAddress((void**)&q,   g_q);
    cudaGetSymbolAddress((void**)&k,   g_k);
    cudaGetSymbolAddress((void**)&v,   g_v);
    cudaGetSymbolAddress((void**)&ctx, g_ctx);
    cudaGetSymbolAddress((void**)&t0,  g_t0);
    cudaGetSymbolAddress((void**)&x1,  g_x1);
    cudaGetSymbolAddress((void**)&ffh, g_ffh);
    cudaGetSymbolAddress((void**)&ff2, g_ff2);

    const dim3 blk(256);
    const dim3 gD (DM  / 128, NROWS / 128);   // (8, 64)
    const dim3 gM (MFF / 128, NROWS / 128);   // (32, 64)

    // Q/K/V projections
    sgemm<0><<<gD, blk>>>(x, Wq, nullptr, q, NROWS, DM, DM);
    sgemm<0><<<gD, blk>>>(x, Wk, nullptr, k, NROWS, DM, DM);
    sgemm<0><<<gD, blk>>>(x, Wv, nullptr, v, NROWS, DM, DM);

    // Attention (dynamic smem > 48KB needs opt-in; idempotent, capture-safe)
    cudaFuncSetAttribute(attn_kernel,
                         cudaFuncAttributeMaxDynamicSharedMemorySize,
                         ATT_SMEM_BYTES);
    attn_kernel<<<dim3(SEQ / 64, NH, NB), blk, ATT_SMEM_BYTES>>>(q, k, v, mask, ctx);

    // Output projection + residual LN
    sgemm<0><<<gD, blk>>>(ctx, Wo, nullptr, t0, NROWS, DM, DM);
    add_ln_kernel<<<NROWS, blk>>>(t0, x, g1, be1, x1);

    // FFN
    sgemm<3><<<gM, blk>>>(x1, W1, b1, ffh, NROWS, MFF, DM);   // bias + relu
    sgemm<1><<<gD, blk>>>(ffh, W2, b2, ff2, NROWS, DM, MFF);  // bias

    // Final residual LN -> d_out
    add_ln_kernel<<<NROWS, blk>>>(ff2, x1, g2, be2, out);
}

// round 6
// speedup vs baseline: 1.5566x; 1.5566x over previous
#include <cuda_runtime.h>
#include <cuda_bf16.h>
#include <cstdint>

// ============================================================================
// EncoderLayer: B=4, S=2048, D=1024, H=16, HD=64, M=4096
// GEMMs via mma.sync bf16x3-split (sm_80-baseline PTX); fp32 flash attention.
// ============================================================================

#define NROWS 8192
#define DM    1024
#define MFF   4096
#define SEQ   2048
#define NB    4
#define NH    16

// ---------------- scratch (device globals; no allocation) -------------------
// NOTE: explicit 256B alignment — cp.async/float4 paths require >=16B.
__device__ __align__(256) float g_q  [NROWS * DM];
__device__ __align__(256) float g_k  [NROWS * DM];
__device__ __align__(256) float g_v  [NROWS * DM];
__device__ __align__(256) float g_ctx[NROWS * DM];
__device__ __align__(256) float g_t0 [NROWS * DM];
__device__ __align__(256) float g_x1 [NROWS * DM];
__device__ __align__(256) float g_ffh[(size_t)NROWS * MFF];
__device__ __align__(256) float g_ff2[NROWS * DM];
__device__ __align__(256) __nv_bfloat16 g_ah[(size_t)NROWS * MFF];
__device__ __align__(256) __nv_bfloat16 g_al[(size_t)NROWS * MFF];
__device__ __align__(256) __nv_bfloat16 g_wh[(size_t)MFF * DM];
__device__ __align__(256) __nv_bfloat16 g_wl[(size_t)MFF * DM];

// ---------------- PTX helpers (baseline sm_80+ features only) ---------------
__device__ __forceinline__ uint32_t smem_u32(const void* p) {
    uint32_t a;
    asm("{ .reg .u64 t; cvta.to.shared.u64 t, %1; cvt.u32.u64 %0, t; }"
        : "=r"(a) : "l"(p));
    return a;
}
#define CP16(s, g) \
    asm volatile("cp.async.cg.shared.global [%0], [%1], 16;" :: "r"(s), "l"(g))
#define CP_COMMIT() asm volatile("cp.async.commit_group;" ::: "memory")
#define CP_WAIT1()  asm volatile("cp.async.wait_group 1;" ::: "memory")
#define CP_WAIT0()  asm volatile("cp.async.wait_group 0;" ::: "memory")

#define LDSM4(r, addr) \
    asm volatile("ldmatrix.sync.aligned.m8n8.x4.shared.b16 {%0,%1,%2,%3}, [%4];" \
        : "=r"((r)[0]), "=r"((r)[1]), "=r"((r)[2]), "=r"((r)[3]) : "r"(addr))

#define MMA_BF16(d, a, b0v, b1v) \
    asm volatile("mma.sync.aligned.m16n8k16.row.col.f32.bf16.bf16.f32 " \
        "{%0,%1,%2,%3}, {%4,%5,%6,%7}, {%8,%9}, {%0,%1,%2,%3};" \
        : "+f"((d)[0]), "+f"((d)[1]), "+f"((d)[2]), "+f"((d)[3]) \
        : "r"((a)[0]), "r"((a)[1]), "r"((a)[2]), "r"((a)[3]), "r"(b0v), "r"(b1v))

// ---------------- mma.sync GEMM: C[M,N] = A[M,K] * Wt[N,K]^T ----------------
// A as bf16 hi/lo [M,K]; W as bf16 hi/lo [N,K] (pre-transposed). fp32 accum.
// Block 128x128, BK=32, 8 warps (4m x 2n), warp tile 32x64.
// Smem rows: 32 bf16 (64B) padded to 80B (conflict-free ldmatrix, 16B-aligned).
// 3-stage cp.async pipeline, exact wait_group accounting.
// MODE bit0 = +bias, bit1 = relu.
#define BK 32
#define ROWB 80                     // padded row bytes
#define MAT_BYTES (128 * ROWB)      // 10240 per matrix (Ah/Al/Bh/Bl)
#define STAGE_BYTES (4 * MAT_BYTES) // 40960
#define NSTAGE 3
#define GEMM_SMEM (NSTAGE * STAGE_BYTES)

template<int MODE>
__global__ __launch_bounds__(256) void gemm_mma(
    const __nv_bfloat16* __restrict__ Ah, const __nv_bfloat16* __restrict__ Al,
    const __nv_bfloat16* __restrict__ Bh, const __nv_bfloat16* __restrict__ Bl,
    const float* __restrict__ bias, float* __restrict__ C,
    int M, int N, int K)
{
    extern __shared__ __align__(16) char smem[];
    const uint32_t sb = smem_u32(smem);
    const int tid  = threadIdx.x;
    const int lane = tid & 31;
    const int wid  = tid >> 5;
    const int warp_m = wid & 3;       // 0..3 -> 32-row slice
    const int warp_n = wid >> 2;      // 0..1 -> 64-col slice
    const int m0 = blockIdx.y * 128;
    const int n0 = blockIdx.x * 128;
    const int T = K / BK;

    // loader: k-tile kt -> stage slot (commits exactly one group)
    auto load_tile = [&](int kt, int slot) {
        const uint32_t base = sb + slot * STAGE_BYTES;
        const size_t kb = (size_t)kt * BK;
        #pragma unroll
        for (int it = 0; it < 2; it++) {          // A: 128 rows x 4 chunks
            int c = tid + it * 256;
            int row = c >> 2, ch = c & 3;
            uint32_t so = base + row * ROWB + ch * 16;
            size_t go = ((size_t)(m0 + row) * K + kb) * 2 + ch * 16;
            CP16(so,             (const char*)Ah + go);
            CP16(so + MAT_BYTES, (const char*)Al + go);
        }
        #pragma unroll
        for (int it = 0; it < 2; it++) {          // B: 128 rows x 4 chunks
            int c = tid + it * 256;
            int row = c >> 2, ch = c & 3;
            uint32_t so = base + 2 * MAT_BYTES + row * ROWB + ch * 16;
            size_t go = ((size_t)(n0 + row) * K + kb) * 2 + ch * 16;
            CP16(so,             (const char*)Bh + go);
            CP16(so + MAT_BYTES, (const char*)Bl + go);
        }
        CP_COMMIT();
    };

    float acc[2][8][4];
    #pragma unroll
    for (int mt = 0; mt < 2; mt++)
        #pragma unroll
        for (int nt = 0; nt < 8; nt++)
            #pragma unroll
            for (int e = 0; e < 4; e++) acc[mt][nt][e] = 0.f;

    load_tile(0, 0);
    load_tile(1, 1);

    const uint32_t lrow  = (uint32_t)(lane & 15);
    const uint32_t lhalf = (uint32_t)((lane >> 4) << 4);

    for (int kt = 0; kt < T; kt++) {
        // tile kt must be resident; tile kt+1 (if committed) may still fly
        if (kt + 1 < T) { CP_WAIT1(); } else { CP_WAIT0(); }
        __syncthreads();   // also fences prior-iteration smem reads vs reuse
        if (kt + 2 < T) load_tile(kt + 2, (kt + 2) % NSTAGE);

        const uint32_t sA = sb + (kt % NSTAGE) * STAGE_BYTES;
        const uint32_t sB = sA + 2 * MAT_BYTES;

        #pragma unroll
        for (int ks = 0; ks < 2; ks++) {
            uint32_t ah[2][4], al[2][4], bh[4][4], bl[4][4];
            #pragma unroll
            for (int mt = 0; mt < 2; mt++) {
                uint32_t ad = sA + (warp_m * 32 + mt * 16 + lrow) * ROWB
                            + lhalf + ks * 32;
                LDSM4(ah[mt], ad);
                LDSM4(al[mt], ad + MAT_BYTES);
            }
            #pragma unroll
            for (int p = 0; p < 4; p++) {
                uint32_t bd = sB + (warp_n * 64 + p * 16 + lrow) * ROWB
                            + lhalf + ks * 32;
                LDSM4(bh[p], bd);
                LDSM4(bl[p], bd + MAT_BYTES);
            }
            #pragma unroll
            for (int mt = 0; mt < 2; mt++)
                #pragma unroll
                for (int nt = 0; nt < 8; nt++) {
                    const int p = nt >> 1, s = nt & 1;
                    MMA_BF16(acc[mt][nt], ah[mt], bh[p][s], bh[p][s + 2]);
                    MMA_BF16(acc[mt][nt], ah[mt], bl[p][s], bl[p][s + 2]);
                    MMA_BF16(acc[mt][nt], al[mt], bh[p][s], bh[p][s + 2]);
                }
        }
    }

    // epilogue
    float* Cb = C + (size_t)(m0 + warp_m * 32) * N + n0 + warp_n * 64;
    const int cr = lane >> 2, cc = (lane & 3) * 2;
    #pragma unroll
    for (int mt = 0; mt < 2; mt++)
        #pragma unroll
        for (int nt = 0; nt < 8; nt++) {
            const int col = nt * 8 + cc;
            float v0 = acc[mt][nt][0], v1 = acc[mt][nt][1];
            float v2 = acc[mt][nt][2], v3 = acc[mt][nt][3];
            if (MODE & 1) {
                const float* bp = bias + n0 + warp_n * 64 + col;
                v0 += bp[0]; v1 += bp[1]; v2 += bp[0]; v3 += bp[1];
            }
            if (MODE & 2) {
                v0 = fmaxf(v0, 0.f); v1 = fmaxf(v1, 0.f);
                v2 = fmaxf(v2, 0.f); v3 = fmaxf(v3, 0.f);
            }
            float2* p0 = (float2*)(Cb + (size_t)(mt * 16 + cr) * N + col);
            float2* p1 = (float2*)(Cb + (size_t)(mt * 16 + cr + 8) * N + col);
            *p0 = make_float2(v0, v1);
            *p1 = make_float2(v2, v3);
        }
}

// ---------------- fp32 -> bf16 hi/lo split ----------------------------------
__global__ __launch_bounds__(256) void split_kernel(
    const float4* __restrict__ a, __nv_bfloat162* __restrict__ hi,
    __nv_bfloat162* __restrict__ lo, int n4)
{
    int i = blockIdx.x * 256 + threadIdx.x;
    if (i >= n4) return;
    float4 v = a[i];
    __nv_bfloat16 hx = __float2bfloat16(v.x), hy = __float2bfloat16(v.y);
    __nv_bfloat16 hz = __float2bfloat16(v.z), hw = __float2bfloat16(v.w);
    __nv_bfloat162 h01, h23, l01, l23;
    h01.x = hx; h01.y = hy; h23.x = hz; h23.y = hw;
    l01.x = __float2bfloat16(v.x - __bfloat162float(hx));
    l01.y = __float2bfloat16(v.y - __bfloat162float(hy));
    l23.x = __float2bfloat16(v.z - __bfloat162float(hz));
    l23.y = __float2bfloat16(v.w - __bfloat162float(hw));
    hi[2 * i] = h01; hi[2 * i + 1] = h23;
    lo[2 * i] = l01; lo[2 * i + 1] = l23;
}

// ---------------- W[K,N] -> Wt hi/lo [N,K] (transpose + split) --------------
__global__ __launch_bounds__(256) void tsplit_kernel(
    const float* __restrict__ W, __nv_bfloat16* __restrict__ th,
    __nv_bfloat16* __restrict__ tl, int K, int N)
{
    __shared__ float t[32][33];
    const int k0 = blockIdx.x * 32, n0 = blockIdx.y * 32;
    const int x = threadIdx.x & 31, y = threadIdx.x >> 5;   // 32 x 8
    #pragma unroll
    for (int i = 0; i < 4; i++)
        t[y + i * 8][x] = W[(size_t)(k0 + y + i * 8) * N + n0 + x];
    __syncthreads();
    #pragma unroll
    for (int i = 0; i < 4; i++) {
        float v = t[x][y + i * 8];
        __nv_bfloat16 h = __float2bfloat16(v);
        size_t o = (size_t)(n0 + y + i * 8) * K + k0 + x;
        th[o] = h;
        tl[o] = __float2bfloat16(v - __bfloat162float(h));
    }
}

// ---------------- flash attention (fp32) -------------------------------------
#define ATT_LD 65
#define ATT_SMEM_FLOATS (4 * 64 * ATT_LD + 3 * 64)
#define ATT_SMEM_BYTES  (ATT_SMEM_FLOATS * 4)

__global__ __launch_bounds__(256) void attn_kernel(
    const float* __restrict__ q, const float* __restrict__ k,
    const float* __restrict__ v, const unsigned char* __restrict__ mask,
    float* __restrict__ ctx)
{
    extern __shared__ float sm[];
    float* Qst = sm;
    float* Kst = Qst + 64 * ATT_LD;
    float* Vs  = Kst + 64 * ATT_LD;
    float* Ss  = Vs  + 64 * ATT_LD;
    float* m_s = Ss  + 64 * ATT_LD;
    float* l_s = m_s + 64;
    float* c_s = l_s + 64;

    const int t  = threadIdx.x;
    const int qt = blockIdx.x, h = blockIdx.y, b = blockIdx.z;
    const int s0 = qt * 64;
    const int tx = t & 15, ty = t >> 4;
    const float scale = 0.03125f;

    const float* qbase = q + ((size_t)b * SEQ + s0) * DM + h * 64;
    const float* kbase = k + (size_t)b * SEQ * DM + h * 64;
    const float* vbase = v + (size_t)b * SEQ * DM + h * 64;

    #pragma unroll
    for (int i = 0; i < 16; i++) {
        int id = t + i * 256;
        int r = id >> 6, d = id & 63;
        Qst[d * ATT_LD + r] = qbase[(size_t)r * DM + d] * scale;
    }
    if (t < 64) { m_s[t] = -1e30f; l_s[t] = 0.f; }

    float acc[4][4];
    #pragma unroll
    for (int i = 0; i < 4; i++)
        #pragma unroll
        for (int j = 0; j < 4; j++) acc[i][j] = 0.f;

    for (int kt = 0; kt < 32; kt++) {
        __syncthreads();
        #pragma unroll
        for (int i = 0; i < 16; i++) {
            int id = t + i * 256;
            int r = id >> 6, d = id & 63;
            size_t goff = (size_t)(kt * 64 + r) * DM + d;
            Kst[d * ATT_LD + r] = kbase[goff];
            Vs [r * ATT_LD + d] = vbase[goff];
        }
        __syncthreads();

        float sc[4][4];
        #pragma unroll
        for (int i = 0; i < 4; i++)
            #pragma unroll
            for (int j = 0; j < 4; j++) sc[i][j] = 0.f;
        #pragma unroll 8
        for (int d = 0; d < 64; d++) {
            float qv[4], kv[4];
            #pragma unroll
            for (int i = 0; i < 4; i++) qv[i] = Qst[d * ATT_LD + ty * 4 + i];
            #pragma unroll
            for (int j = 0; j < 4; j++) kv[j] = Kst[d * ATT_LD + tx * 4 + j];
            #pragma unroll
            for (int i = 0; i < 4; i++)
                #pragma unroll
                for (int j = 0; j < 4; j++)
                    sc[i][j] = fmaf(qv[i], kv[j], sc[i][j]);
        }
        const unsigned char* mrow =
            mask + ((size_t)b * SEQ + s0 + ty * 4) * SEQ + kt * 64 + tx * 4;
        #pragma unroll
        for (int i = 0; i < 4; i++)
            #pragma unroll
            for (int j = 0; j < 4; j++) {
                float s = sc[i][j];
                if (mrow[(size_t)i * SEQ + j]) s = -1e9f;
                Ss[(ty * 4 + i) * ATT_LD + tx * 4 + j] = s;
            }
        __syncthreads();

        {
            const int r = t >> 2, qd = t & 3;
            float mold = m_s[r];
            float sv[16];
            float tm = -1e30f;
            #pragma unroll
            for (int c = 0; c < 16; c++) {
                sv[c] = Ss[r * ATT_LD + qd * 16 + c];
                tm = fmaxf(tm, sv[c]);
            }
            tm = fmaxf(tm, __shfl_xor_sync(0xffffffffu, tm, 1));
            tm = fmaxf(tm, __shfl_xor_sync(0xffffffffu, tm, 2));
            float mnew = fmaxf(mold, tm);
            float corr = __expf(mold - mnew);
            float ls = 0.f;
            #pragma unroll
            for (int c = 0; c < 16; c++) {
                float p = __expf(sv[c] - mnew);
                Ss[r * ATT_LD + qd * 16 + c] = p;
                ls += p;
            }
            ls += __shfl_xor_sync(0xffffffffu, ls, 1);
            ls += __shfl_xor_sync(0xffffffffu, ls, 2);
            if (qd == 0) {
                m_s[r] = mnew;
                l_s[r] = l_s[r] * corr + ls;
                c_s[r] = corr;
            }
        }
        __syncthreads();

        float cr[4];
        #pragma unroll
        for (int i = 0; i < 4; i++) cr[i] = c_s[ty * 4 + i];
        #pragma unroll
        for (int i = 0; i < 4; i++)
            #pragma unroll
            for (int j = 0; j < 4; j++) acc[i][j] *= cr[i];
        #pragma unroll 8
        for (int c = 0; c < 64; c++) {
            float pv[4], vv[4];
            #pragma unroll
            for (int i = 0; i < 4; i++) pv[i] = Ss[(ty * 4 + i) * ATT_LD + c];
            #pragma unroll
            for (int j = 0; j < 4; j++) vv[j] = Vs[c * ATT_LD + tx * 4 + j];
            #pragma unroll
            for (int i = 0; i < 4; i++)
                #pragma unroll
                for (int j = 0; j < 4; j++)
                    acc[i][j] = fmaf(pv[i], vv[j], acc[i][j]);
        }
    }

    float* obase = ctx + ((size_t)b * SEQ + s0) * DM + h * 64;
    #pragma unroll
    for (int i = 0; i < 4; i++) {
        const int r = ty * 4 + i;
        const float inv_l = 1.0f / l_s[r];
        #pragma unroll
        for (int j = 0; j < 4; j++)
            obase[(size_t)r * DM + tx * 4 + j] = acc[i][j] * inv_l;
    }
}

// ---------------- residual + LayerNorm ---------------------------------------
__global__ __launch_bounds__(256) void add_ln_kernel(
    const float* __restrict__ a, const float* __restrict__ res,
    const float* __restrict__ gmm, const float* __restrict__ beta,
    float* __restrict__ out)
{
    const int row = blockIdx.x;
    const int t = threadIdx.x;
    const size_t base = (size_t)row * DM;
    float v[4];
    float s = 0.f, s2 = 0.f;
    #pragma unroll
    for (int i = 0; i < 4; i++) {
        int c = t + i * 256;
        float x = a[base + c] + res[base + c];
        v[i] = x; s += x; s2 += x * x;
    }
    #pragma unroll
    for (int o = 16; o > 0; o >>= 1) {
        s  += __shfl_down_sync(0xffffffffu, s,  o);
        s2 += __shfl_down_sync(0xffffffffu, s2, o);
    }
    __shared__ float sh[18];
    const int w = t >> 5;
    if ((t & 31) == 0) { sh[w] = s; sh[8 + w] = s2; }
    __syncthreads();
    if (t == 0) {
        float ts = 0.f, ts2 = 0.f;
        #pragma unroll
        for (int i = 0; i < 8; i++) { ts += sh[i]; ts2 += sh[8 + i]; }
        float mu  = ts * (1.0f / DM);
        float var = ts2 * (1.0f / DM) - mu * mu;
        sh[16] = mu;
        sh[17] = rsqrtf(var + 1e-5f);
    }
    __syncthreads();
    const float mu = sh[16], rs = sh[17];
    #pragma unroll
    for (int i = 0; i < 4; i++) {
        int c = t + i * 256;
        out[base + c] = (v[i] - mu) * rs * gmm[c] + beta[c];
    }
}

// ---------------- kernel_launch ---------------------------------------------
extern "C" void kernel_launch(void* const* d_in, const int* in_sizes, int n_in,
                              void* d_out, int out_size)
{
    (void)in_sizes; (void)n_in; (void)out_size;
    const float* x  = (const float*)d_in[0];
    const unsigned char* mask = (const unsigned char*)d_in[1];
    const float* Wq = (const float*)d_in[2];
    const float* Wk = (const float*)d_in[3];
    const float* Wv = (const float*)d_in[4];
    const float* Wo = (const float*)d_in[5];
    const float* W1 = (const float*)d_in[6];
    const float* b1 = (const float*)d_in[7];
    const float* W2 = (const float*)d_in[8];
    const float* b2 = (const float*)d_in[9];
    const float* g1  = (const float*)d_in[10];
    const float* be1 = (const float*)d_in[11];
    const float* g2  = (const float*)d_in[12];
    const float* be2 = (const float*)d_in[13];
    float* out = (float*)d_out;

    float *q, *k, *v, *ctx, *t0, *x1, *ffh, *ff2;
    __nv_bfloat16 *ah, *al, *wh, *wl;
    cudaGetSymbolAddress((void**)&q,   g_q);
    cudaGetSymbolAddress((void**)&k,   g_k);
    cudaGetSymbolAddress((void**)&v,   g_v);
    cudaGetSymbolAddress((void**)&ctx, g_ctx);
    cudaGetSymbolAddress((void**)&t0,  g_t0);
    cudaGetSymbolAddress((void**)&x1,  g_x1);
    cudaGetSymbolAddress((void**)&ffh, g_ffh);
    cudaGetSymbolAddress((void**)&ff2, g_ff2);
    cudaGetSymbolAddress((void**)&ah,  g_ah);
    cudaGetSymbolAddress((void**)&al,  g_al);
    cudaGetSymbolAddress((void**)&wh,  g_wh);
    cudaGetSymbolAddress((void**)&wl,  g_wl);

    cudaFuncSetAttribute(gemm_mma<0>, cudaFuncAttributeMaxDynamicSharedMemorySize, GEMM_SMEM);
    cudaFuncSetAttribute(gemm_mma<1>, cudaFuncAttributeMaxDynamicSharedMemorySize, GEMM_SMEM);
    cudaFuncSetAttribute(gemm_mma<3>, cudaFuncAttributeMaxDynamicSharedMemorySize, GEMM_SMEM);
    cudaFuncSetAttribute(attn_kernel, cudaFuncAttributeMaxDynamicSharedMemorySize, ATT_SMEM_BYTES);

    const dim3 blk(256);
    const int nD4 = NROWS * DM / 4;
    const int nF4 = NROWS * MFF / 4;
    const dim3 gemD(DM / 128, NROWS / 128);   // (8, 64)
    const dim3 gemM(MFF / 128, NROWS / 128);  // (32, 64)

    // x split (shared by Q/K/V projections)
    split_kernel<<<nD4 / 256, blk>>>((const float4*)x, (__nv_bfloat162*)ah,
                                     (__nv_bfloat162*)al, nD4);
    // Q
    tsplit_kernel<<<dim3(DM / 32, DM / 32), blk>>>(Wq, wh, wl, DM, DM);
    gemm_mma<0><<<gemD, blk, GEMM_SMEM>>>(ah, al, wh, wl, nullptr, q, NROWS, DM, DM);
    // K
    tsplit_kernel<<<dim3(DM / 32, DM / 32), blk>>>(Wk, wh, wl, DM, DM);
    gemm_mma<0><<<gemD, blk, GEMM_SMEM>>>(ah, al, wh, wl, nullptr, k, NROWS, DM, DM);
    // V
    tsplit_kernel<<<dim3(DM / 32, DM / 32), blk>>>(Wv, wh, wl, DM, DM);
    gemm_mma<0><<<gemD, blk, GEMM_SMEM>>>(ah, al, wh, wl, nullptr, v, NROWS, DM, DM);

    // attention
    attn_kernel<<<dim3(SEQ / 64, NH, NB), blk, ATT_SMEM_BYTES>>>(q, k, v, mask, ctx);

    // Wo projection + residual LN
    split_kernel<<<nD4 / 256, blk>>>((const float4*)ctx, (__nv_bfloat162*)ah,
                                     (__nv_bfloat162*)al, nD4);
    tsplit_kernel<<<dim3(DM / 32, DM / 32), blk>>>(Wo, wh, wl, DM, DM);
    gemm_mma<0><<<gemD, blk, GEMM_SMEM>>>(ah, al, wh, wl, nullptr, t0, NROWS, DM, DM);
    add_ln_kernel<<<NROWS, blk>>>(t0, x, g1, be1, x1);

    // FFN1: relu(x1 @ W1 + b1)
    split_kernel<<<nD4 / 256, blk>>>((const float4*)x1, (__nv_bfloat162*)ah,
                                     (__nv_bfloat162*)al, nD4);
    tsplit_kernel<<<dim3(DM / 32, MFF / 32), blk>>>(W1, wh, wl, DM, MFF);
    gemm_mma<3><<<gemM, blk, GEMM_SMEM>>>(ah, al, wh, wl, b1, ffh, NROWS, MFF, DM);

    // FFN2: ffh @ W2 + b2
    split_kernel<<<nF4 / 256, blk>>>((const float4*)ffh, (__nv_bfloat162*)ah,
                                     (__nv_bfloat162*)al, nF4);
    tsplit_kernel<<<dim3(MFF / 32, DM / 32), blk>>>(W2, wh, wl, MFF, DM);
    gemm_mma<1><<<gemD, blk, GEMM_SMEM>>>(ah, al, wh, wl, b2, ff2, NROWS, DM, MFF);

    add_ln_kernel<<<NROWS, blk>>>(ff2, x1, g2, be2, out);
}